// round 1
// baseline (speedup 1.0000x reference)
#include <cuda_runtime.h>
#include <cuda_bf16.h>

#define N        1024
#define ED       256
#define HD       128
#define TS       32     // pair-tile size (i and j)
#define PAD      132    // padded smem row stride (floats), 16B-aligned, breaks bank conflicts

// ---------------- scratch (no allocation allowed) ----------------
__device__ float g_context[HD];
__device__ float g_queries[N * HD];
__device__ float g_keys[N * HD];
__device__ float g_qp[N * HD];
__device__ float g_kp[N * HD];

// ---------------- kernel A: context = relu(emb @ Wc + bc) ----------------
__global__ void ctx_kernel(const float* __restrict__ emb,
                           const float* __restrict__ Wc,
                           const float* __restrict__ bc) {
    int h = threadIdx.x;            // 128 threads
    float s = bc[h];
    #pragma unroll 8
    for (int e = 0; e < ED; e++)
        s = fmaf(emb[e], Wc[e * HD + h], s);
    g_context[h] = fmaxf(s, 0.0f);
}

// ---------------- kernel B: queries/keys = prev @ W{q,k} + b + context ----
__global__ void qk_kernel(const float* __restrict__ prev,
                          const float* __restrict__ Wq,
                          const float* __restrict__ bq,
                          const float* __restrict__ Wk,
                          const float* __restrict__ bk) {
    __shared__ float row[ED];
    int i = blockIdx.x;
    int t = threadIdx.x;            // 256 threads
    row[t] = prev[i * ED + t];
    __syncthreads();
    if (t < HD) {
        float s = bq[t] + g_context[t];
        #pragma unroll 8
        for (int e = 0; e < ED; e++)
            s = fmaf(row[e], Wq[e * HD + t], s);
        g_queries[i * HD + t] = s;
    } else {
        int h = t - HD;
        float s = bk[h] + g_context[h];
        #pragma unroll 8
        for (int e = 0; e < ED; e++)
            s = fmaf(row[e], Wk[e * HD + h], s);
        g_keys[i * HD + h] = s;
    }
}

// ---------------- kernel B2: qp = queries@W1[:h] + b1 ; kp = keys@W1[h:] ---
__global__ void proj_kernel(const float* __restrict__ W1,
                            const float* __restrict__ b1) {
    __shared__ float qrow[HD];
    __shared__ float krow[HD];
    int i = blockIdx.x;
    int t = threadIdx.x;            // 256 threads
    if (t < HD) qrow[t] = g_queries[i * HD + t];
    else        krow[t - HD] = g_keys[i * HD + (t - HD)];
    __syncthreads();
    if (t < HD) {
        float s = b1[t];            // fold b1 into qp only
        #pragma unroll 8
        for (int e = 0; e < HD; e++)
            s = fmaf(qrow[e], W1[e * HD + t], s);
        g_qp[i * HD + t] = s;
    } else {
        int h = t - HD;
        float s = 0.0f;
        #pragma unroll 8
        for (int e = 0; e < HD; e++)
            s = fmaf(krow[e], W1[(HD + e) * HD + h], s);
        g_kp[i * HD + h] = s;
    }
}

// ---------------- kernel C: pair scores, triu(i<j) row-major ---------------
__global__ void __launch_bounds__(256, 2)
pair_kernel(const float* __restrict__ W2,
            const float* __restrict__ b2,
            float* __restrict__ out) {
    int jt = blockIdx.x, it = blockIdx.y;
    if (jt < it) return;            // tile entirely below diagonal

    __shared__ __align__(16) float qs[TS * PAD];
    __shared__ __align__(16) float ks[TS * PAD];
    __shared__ __align__(16) float w2s[HD];

    int t = threadIdx.x;            // 256 threads
    for (int idx = t; idx < TS * HD; idx += 256) {
        int r = idx >> 7, h = idx & (HD - 1);
        qs[r * PAD + h] = g_qp[(it * TS + r) * HD + h];
        ks[r * PAD + h] = g_kp[(jt * TS + r) * HD + h];
    }
    if (t < HD) w2s[t] = W2[t];
    __syncthreads();

    int tx = t & 15, ty = t >> 4;   // 16x16 thread tile
    int i0 = ty * 2, j0 = tx * 2;   // 2x2 pairs per thread

    float a00 = 0.f, a01 = 0.f, a10 = 0.f, a11 = 0.f;

    const float4* q0p = (const float4*)&qs[i0 * PAD];
    const float4* q1p = (const float4*)&qs[(i0 + 1) * PAD];
    const float4* k0p = (const float4*)&ks[j0 * PAD];
    const float4* k1p = (const float4*)&ks[(j0 + 1) * PAD];
    const float4* wp  = (const float4*)w2s;

    #pragma unroll
    for (int h4 = 0; h4 < HD / 4; h4++) {
        float4 q0 = q0p[h4];
        float4 q1 = q1p[h4];
        float4 k0 = k0p[h4];
        float4 k1 = k1p[h4];
        float4 w  = wp[h4];
        #define STEP(c) \
            a00 = fmaf(fmaxf(q0.c + k0.c, 0.f), w.c, a00); \
            a01 = fmaf(fmaxf(q0.c + k1.c, 0.f), w.c, a01); \
            a10 = fmaf(fmaxf(q1.c + k0.c, 0.f), w.c, a10); \
            a11 = fmaf(fmaxf(q1.c + k1.c, 0.f), w.c, a11);
        STEP(x) STEP(y) STEP(z) STEP(w)
        #undef STEP
    }

    float bias = b2[0];
    int ibase = it * TS + i0;
    int jbase = jt * TS + j0;
    float acc[2][2] = {{a00, a01}, {a10, a11}};
    #pragma unroll
    for (int a = 0; a < 2; a++) {
        int i = ibase + a;
        // row-major triu offset: i*N - i*(i+1)/2 + (j - i - 1)
        int rowoff = i * N - ((i * (i + 1)) >> 1) - i - 1;
        #pragma unroll
        for (int b = 0; b < 2; b++) {
            int j = jbase + b;
            if (i < j)
                out[rowoff + j] = acc[a][b] + bias;
        }
    }
}

// ---------------- launch ----------------
extern "C" void kernel_launch(void* const* d_in, const int* in_sizes, int n_in,
                              void* d_out, int out_size) {
    const float* emb  = (const float*)d_in[0];   // next_state_embedding [256]
    const float* prev = (const float*)d_in[1];   // prev_variable_embeddings [1024,256]
    const float* Wq   = (const float*)d_in[2];
    const float* bq   = (const float*)d_in[3];
    const float* Wk   = (const float*)d_in[4];
    const float* bk   = (const float*)d_in[5];
    const float* Wc   = (const float*)d_in[6];
    const float* bc   = (const float*)d_in[7];
    const float* W1   = (const float*)d_in[8];
    const float* b1   = (const float*)d_in[9];
    const float* W2   = (const float*)d_in[10];
    const float* b2   = (const float*)d_in[11];
    float* out = (float*)d_out;

    ctx_kernel<<<1, HD>>>(emb, Wc, bc);
    qk_kernel<<<N, 256>>>(prev, Wq, bq, Wk, bk);
    proj_kernel<<<N, 256>>>(W1, b1);
    dim3 grid(N / TS, N / TS);
    pair_kernel<<<grid, 256>>>(W2, b2, out);
}